// round 16
// baseline (speedup 1.0000x reference)
#include <cuda_runtime.h>
#include <cuda_fp16.h>
#include <math.h>
#include <stdint.h>

// ---------------- problem constants ----------------
#define B_  4
#define N_  2048
#define C_  64
#define HS_ 512
#define H_  8
#define D_  64
#define M_  (B_*N_)
#define EPS 1e-6f
#define QSCALE 0.1803368801111144f   // log2(e)/8

#define QSZ (B_*H_*N_*D_)

// ---------------- scratch ----------------
__device__ __half g_qh[QSZ];          // [b*h][n][d], pre-scaled log2e/8
__device__ __half g_kh[QSZ];
__device__ __half g_vh[QSZ];
__device__ __half g_wT [1536 * 64];   // WqkvT fp16 [n][k]
__device__ __half g_woT[64 * 512];
__device__ __half g_w1T[64 * 64];
__device__ __half g_w2T[64 * 64];
__device__ __half g_ctxh[M_ * HS_];   // attention output fp16 (b,n,h*64+d)

__device__ __forceinline__ uint32_t smem_u32(const void* p) {
    uint32_t a;
    asm("{ .reg .u64 t; cvta.to.shared.u64 t, %1; cvt.u32.u64 %0, t; }" : "=r"(a) : "l"(p));
    return a;
}
__device__ __forceinline__ void mma16816(float c[4], const uint32_t a[4],
                                         uint32_t b0, uint32_t b1) {
    asm volatile("mma.sync.aligned.m16n8k16.row.col.f32.f16.f16.f32 "
        "{%0,%1,%2,%3}, {%4,%5,%6,%7}, {%8,%9}, {%0,%1,%2,%3};"
        : "+f"(c[0]), "+f"(c[1]), "+f"(c[2]), "+f"(c[3])
        : "r"(a[0]), "r"(a[1]), "r"(a[2]), "r"(a[3]), "r"(b0), "r"(b1));
}
// f16-accumulator HMMA
__device__ __forceinline__ void mma16816h(uint32_t c[2], const uint32_t a[4],
                                          uint32_t b0, uint32_t b1) {
    asm volatile("mma.sync.aligned.m16n8k16.row.col.f16.f16.f16.f16 "
        "{%0,%1}, {%2,%3,%4,%5}, {%6,%7}, {%0,%1};"
        : "+r"(c[0]), "+r"(c[1])
        : "r"(a[0]), "r"(a[1]), "r"(a[2]), "r"(a[3]), "r"(b0), "r"(b1));
}
__device__ __forceinline__ void ldm_x4(uint32_t r[4], uint32_t addr) {
    asm volatile("ldmatrix.sync.aligned.m8n8.x4.shared.b16 {%0,%1,%2,%3}, [%4];"
        : "=r"(r[0]), "=r"(r[1]), "=r"(r[2]), "=r"(r[3]) : "r"(addr));
}
__device__ __forceinline__ void ldm_x4_t(uint32_t r[4], uint32_t addr) {
    asm volatile("ldmatrix.sync.aligned.m8n8.x4.trans.shared.b16 {%0,%1,%2,%3}, [%4];"
        : "=r"(r[0]), "=r"(r[1]), "=r"(r[2]), "=r"(r[3]) : "r"(addr));
}
__device__ __forceinline__ uint32_t ex2h2(uint32_t x) {
    asm("ex2.approx.f16x2 %0, %0;" : "+r"(x));
    return x;
}
__device__ __forceinline__ void cpa16(uint32_t dst, const void* src) {
    asm volatile("cp.async.ca.shared.global [%0], [%1], 16;" :: "r"(dst), "l"(src) : "memory");
}
__device__ __forceinline__ float gelu(float v) {
    return 0.5f * v * (1.0f + erff(v * 0.70710678118f));
}

// =====================================================================
// Kernel 0: all weight prep (fp32 -> fp16 transposed)
// =====================================================================
__global__ __launch_bounds__(256) void wt_kernel(
    const float* __restrict__ Wqkv, const float* __restrict__ Wout,
    const float* __restrict__ W1, const float* __restrict__ W2)
{
    int idx = blockIdx.x * 256 + threadIdx.x;   // 139264 total
    if (idx < 98304) {
        int k = idx / 1536, n = idx - k * 1536;
        g_wT[n * 64 + k] = __float2half(Wqkv[idx]);
    } else if (idx < 131072) {
        int i = idx - 98304; int k = i >> 6, n = i & 63;
        g_woT[n * 512 + k] = __float2half(Wout[i]);
    } else if (idx < 135168) {
        int i = idx - 131072; int k = i >> 6, n = i & 63;
        g_w1T[n * 64 + k] = __float2half(W1[i]);
    } else {
        int i = idx - 135168; int k = i >> 6, n = i & 63;
        g_w2T[n * 64 + k] = __float2half(W2[i]);
    }
}

// =====================================================================
// Kernel 1: LN1 + QKV GEMM (fp16 mma). grid (128 m-tiles, 2 j-groups),
// 128 threads.
// =====================================================================
__global__ __launch_bounds__(128) void ln_qkv_kernel(
    const float* __restrict__ x, const float* __restrict__ g1,
    const float* __restrict__ be1, const float* __restrict__ bias)
{
    __shared__ __align__(16) uint32_t Ys[64 * 36];
    __shared__ __align__(16) uint32_t Ws[2][128 * 36];

    const int tid = threadIdx.x, wid = tid >> 5, lane = tid & 31;
    const int qr = lane >> 2, qc = lane & 3;
    const int m0 = blockIdx.x * 64;
    const int jt0 = blockIdx.y * 6;
    const uint32_t* wtw = (const uint32_t*)g_wT;

    auto issueW = [&](int jt, int buf) {
#pragma unroll
        for (int it = 0; it < 8; it++) {
            int cid = tid + 128 * it;               // 1024 chunks of 16B
            int row = cid >> 3, cc = cid & 7;
            cpa16(smem_u32(&Ws[buf][row * 36 + cc * 4]),
                  wtw + ((jt0 + jt) * 128 + row) * 32 + cc * 4);
        }
        asm volatile("cp.async.commit_group;" ::: "memory");
    };
    issueW(0, 0);

    {
        const float g1a = g1[lane], g1b = g1[lane + 32];
        const float bea = be1[lane], beb = be1[lane + 32];
        __half* ysh = (__half*)Ys;
#pragma unroll
        for (int rr = 0; rr < 16; rr++) {
            int row = wid * 16 + rr;
            float a = x[(m0 + row) * 64 + lane];
            float b = x[(m0 + row) * 64 + lane + 32];
            float s = a + b;
#pragma unroll
            for (int o = 16; o; o >>= 1) s += __shfl_xor_sync(0xffffffffu, s, o);
            float mean = s * (1.0f / 64.0f);
            float da = a - mean, db = b - mean;
            float q = da * da + db * db;
#pragma unroll
            for (int o = 16; o; o >>= 1) q += __shfl_xor_sync(0xffffffffu, q, o);
            float rstd = rsqrtf(q * (1.0f / 64.0f) + EPS);
            ysh[row * 72 + lane]      = __float2half(da * rstd * g1a + bea);
            ysh[row * 72 + lane + 32] = __float2half(db * rstd * g1b + beb);
        }
    }
    __syncthreads();

    const uint32_t ys_base = smem_u32(Ys);
    uint32_t a[4][4][4];
#pragma unroll
    for (int m = 0; m < 4; m++)
#pragma unroll
        for (int kc = 0; kc < 4; kc++)
            ldm_x4(a[m][kc], ys_base + (m * 16 + (lane & 15)) * 144
                              + (kc * 16 + (lane >> 4) * 8) * 2);

    for (int jt = 0; jt < 6; jt++) {
        const int buf = jt & 1;
        asm volatile("cp.async.wait_group 0;" ::: "memory");
        __syncthreads();
        if (jt < 5) issueW(jt + 1, buf ^ 1);

        const uint32_t ws_base = smem_u32(&Ws[buf][0]);
        float c[4][4][4] = {};
#pragma unroll
        for (int kcp = 0; kcp < 2; kcp++) {
#pragma unroll
            for (int nb = 0; nb < 4; nb++) {
                uint32_t b[4];
                ldm_x4(b, ws_base + (wid * 32 + nb * 8 + (lane & 7)) * 144
                              + (kcp * 32 + (lane >> 3) * 8) * 2);
#pragma unroll
                for (int m = 0; m < 4; m++) {
                    mma16816(c[m][nb], a[m][2 * kcp],     b[0], b[1]);
                    mma16816(c[m][nb], a[m][2 * kcp + 1], b[2], b[3]);
                }
            }
        }
        const int j0 = (jt0 + jt) * 128;
#pragma unroll
        for (int nb = 0; nb < 4; nb++) {
            int j = j0 + wid * 32 + nb * 8 + qc * 2;
            int sel = j >> 9, head = (j >> 6) & 7, d = j & 63;
            float bj0 = bias[j], bj1 = bias[j + 1];
            float sc = (sel == 0) ? QSCALE : 1.0f;
            __half* dst = (sel == 0) ? g_qh : (sel == 1) ? g_kh : g_vh;
#pragma unroll
            for (int m = 0; m < 4; m++) {
#pragma unroll
                for (int hf = 0; hf < 2; hf++) {
                    int gm = m0 + m * 16 + qr + hf * 8;
                    int bi = gm >> 11, n = gm & 2047;
                    float v0 = (c[m][nb][hf * 2]     + bj0) * sc;
                    float v1 = (c[m][nb][hf * 2 + 1] + bj1) * sc;
                    size_t off = ((size_t)(bi * 8 + head) * 2048 + n) * 64 + d;
                    *(__half2*)(dst + off) = __floats2half2_rn(v0, v1);
                }
            }
        }
    }
}

// =====================================================================
// Kernel 2: flash attention, proven core + 3-stage cp.async pipeline.
// Dynamic smem 63KB: Qs [0,9216) | KV buf b, K/V t at 9216+(2b+t)*9216.
// =====================================================================
#define ATTN_SMEM (9216 + 6 * 9216)   // 64512

__global__ __launch_bounds__(128) void attn_kernel()
{
    extern __shared__ __align__(16) unsigned char dynsm[];
    uint32_t* smw = (uint32_t*)dynsm;
    const uint32_t base = smem_u32(dynsm);

    const int tid = threadIdx.x, wid = tid >> 5, lane = tid & 31;
    const int qr = lane >> 2, qc = lane & 3;
    const int bh = blockIdx.y, q0 = blockIdx.x * 64;
    const uint32_t* qb = (const uint32_t*)(g_qh + (size_t)bh * N_ * D_);
    const __half* kbh = g_kh + (size_t)bh * N_ * D_;
    const __half* vbh = g_vh + (size_t)bh * N_ * D_;

    auto issue = [&](int kt, int buf) {
#pragma unroll
        for (int it = 0; it < 8; it++) {
            int cid = tid + 128 * it;
            int tsel = cid >> 9, r = (cid >> 3) & 63, cc = cid & 7;
            const __half* src = (tsel ? vbh : kbh) + (size_t)(kt * 64 + r) * 64 + cc * 8;
            cpa16(base + 9216 + (buf * 2 + tsel) * 9216 + (r * 36 + cc * 4) * 4, src);
        }
        asm volatile("cp.async.commit_group;" ::: "memory");
    };
    issue(0, 0);
    issue(1, 1);

    // stage Q (64 rows x 32 words)
#pragma unroll
    for (int r = 0; r < 16; r++) {
        int idx = tid + 128 * r; int row = idx >> 5, w = idx & 31;
        smw[row * 36 + w] = qb[(q0 + row) * 32 + w];
    }
    // V ones-extension: words 32..35 of 64 rows x 3 buffers (768 words)
#pragma unroll
    for (int r = 0; r < 6; r++) {
        int idx = tid + 128 * r;
        int buf = idx >> 8, row = (idx >> 2) & 63, w = 32 + (idx & 3);
        smw[(9216 + (buf * 2 + 1) * 9216) / 4 + row * 36 + w] =
            (w == 32) ? 0x00003C00u : 0u;
    }
    __syncthreads();

    uint32_t aq[4][4];
#pragma unroll
    for (int kc = 0; kc < 4; kc++) {
        aq[kc][0] = smw[(wid * 16 + qr) * 36 + kc * 8 + qc];
        aq[kc][1] = smw[(wid * 16 + qr + 8) * 36 + kc * 8 + qc];
        aq[kc][2] = smw[(wid * 16 + qr) * 36 + kc * 8 + 4 + qc];
        aq[kc][3] = smw[(wid * 16 + qr + 8) * 36 + kc * 8 + 4 + qc];
    }

    float oacc[8][4] = {};
    float lsum0 = 0.0f, lsum1 = 0.0f;

    int buf = 0;
    for (int kt = 0; kt < 32; kt++) {
        if (kt < 31) { asm volatile("cp.async.wait_group 1;" ::: "memory"); }
        else         { asm volatile("cp.async.wait_group 0;" ::: "memory"); }
        __syncthreads();
        if (kt < 30) {
            int buf2 = buf + 2; if (buf2 >= 3) buf2 -= 3;
            issue(kt + 2, buf2);
        }

        const uint32_t Kbase = base + 9216 + (buf * 2) * 9216;
        const uint32_t Vbase = Kbase + 9216;

        uint32_t sp[8][2] = {};
#pragma unroll
        for (int nb = 0; nb < 8; nb++) {
            uint32_t rowb = (nb * 8 + (lane & 7)) * 144;
#pragma unroll
            for (int kcp = 0; kcp < 2; kcp++) {
                uint32_t b[4];
                ldm_x4(b, Kbase + rowb + (kcp * 32 + (lane >> 3) * 8) * 2);
                mma16816h(sp[nb], aq[2 * kcp],     b[0], b[1]);
                mma16816h(sp[nb], aq[2 * kcp + 1], b[2], b[3]);
            }
        }

        __half2 t0 = __floats2half2_rn(0.0f, 0.0f), t1 = t0;
#pragma unroll
        for (int nb = 0; nb < 8; nb++) {
            sp[nb][0] = ex2h2(sp[nb][0]);
            sp[nb][1] = ex2h2(sp[nb][1]);
            t0 = __hadd2(t0, *(__half2*)&sp[nb][0]);
            t1 = __hadd2(t1, *(__half2*)&sp[nb][1]);
        }
        lsum0 += __low2float(t0) + __high2float(t0);
        lsum1 += __low2float(t1) + __high2float(t1);

#pragma unroll
        for (int nb = 0; nb < 8; nb++) {
#pragma unroll
            for (int kcp = 0; kcp < 2; kcp++) {
                uint32_t b[4];
                uint32_t row = kcp * 32 + (lane & 7) + (lane >> 3) * 8;
                ldm_x4_t(b, Vbase + row * 144 + nb * 16);
                uint32_t a0[4] = {sp[4 * kcp][0],     sp[4 * kcp][1],
                                  sp[4 * kcp + 1][0], sp[4 * kcp + 1][1]};
                uint32_t a1[4] = {sp[4 * kcp + 2][0], sp[4 * kcp + 2][1],
                                  sp[4 * kcp + 3][0], sp[4 * kcp + 3][1]};
                mma16816(oacc[nb], a0, b[0], b[1]);
                mma16816(oacc[nb], a1, b[2], b[3]);
            }
        }
        if (++buf == 3) buf = 0;
    }

    lsum0 += __shfl_xor_sync(0xffffffffu, lsum0, 1);
    lsum0 += __shfl_xor_sync(0xffffffffu, lsum0, 2);
    lsum1 += __shfl_xor_sync(0xffffffffu, lsum1, 1);
    lsum1 += __shfl_xor_sync(0xffffffffu, lsum1, 2);
    const float inv0 = 1.0f / lsum0, inv1 = 1.0f / lsum1;

    const int bi = bh >> 3, head = bh & 7;
    const int n0 = q0 + wid * 16 + qr;
#pragma unroll
    for (int nb = 0; nb < 8; nb++) {
        const int d = nb * 8 + qc * 2;
        *(__half2*)(g_ctxh + ((size_t)(bi * 2048 + n0)) * 512 + head * 64 + d) =
            __floats2half2_rn(oacc[nb][0] * inv0, oacc[nb][1] * inv0);
        *(__half2*)(g_ctxh + ((size_t)(bi * 2048 + n0 + 8)) * 512 + head * 64 + d) =
            __floats2half2_rn(oacc[nb][2] * inv1, oacc[nb][3] * inv1);
    }
}

// =====================================================================
// Kernel 3: FUSED tail (round-14 proven version: 32-row tiles, K=128
// chunks, double-buffered, W1/W2 prefetch). grid 256, 256 threads.
//   [0,8704)       ctx[0] 32x272B     | y2s (B/C) @0, hs @4608
//   [8704,26112)   wo[0]  64x272B
//   [26112,34816)  ctx[1]
//   [34816,52224)  wo[1]
//   [52224,60416)  x2s 32x64 f32
//   [60416,69632)  W1s 64x144B
//   [69632,78848)  W2s
// =====================================================================
#define FUSED_SMEM 78848

__global__ __launch_bounds__(256) void fused_tail_kernel(
    const float* __restrict__ x, const float* __restrict__ bout,
    const float* __restrict__ g2, const float* __restrict__ be2,
    const float* __restrict__ b1, const float* __restrict__ b2,
    float* __restrict__ out)
{
    extern __shared__ __align__(16) unsigned char dynsm[];
    float* x2s = (float*)(dynsm + 52224);
    const uint32_t base = smem_u32(dynsm);
    const uint32_t y2s_b = base, hs_b = base + 4608;
    const uint32_t w1s_b = base + 60416, w2s_b = base + 69632;

    const int tid = threadIdx.x, wid = tid >> 5, lane = tid & 31;
    const int qr = lane >> 2, qc = lane & 3;
    const int mb = wid & 1, ng = wid >> 1;
    const int m0 = blockIdx.x * 32;

    // prefetch W1/W2 (16KB = 1024 chunks of 16B) as the FIRST group
#pragma unroll
    for (int it = 0; it < 4; it++) {
        int cid = tid + 256 * it;                 // 0..1023
        int sel = cid >> 9, r = (cid >> 3) & 63, cc = cid & 7;
        uint32_t dst = (sel ? w2s_b : w1s_b) + (r * 36 + cc * 4) * 4;
        const uint32_t* src = (const uint32_t*)(sel ? g_w2T : g_w1T) + r * 32 + cc * 4;
        cpa16(dst, src);
    }
    asm volatile("cp.async.commit_group;" ::: "memory");

    auto issueA = [&](int kc, int buf) {
        uint32_t ctx_b = base + buf * 26112;
        uint32_t wo_b  = ctx_b + 8704;
        // ctx: 32 rows x 128 halves = 512 chunks
#pragma unroll
        for (int it = 0; it < 2; it++) {
            int cid = tid + 256 * it;
            int row = cid >> 4, cc = cid & 15;
            cpa16(ctx_b + (row * 68 + cc * 4) * 4,
                  g_ctxh + (size_t)(m0 + row) * 512 + kc * 128 + cc * 8);
        }
        // wo: 64 rows x 128 halves = 1024 chunks
#pragma unroll
        for (int it = 0; it < 4; it++) {
            int cid = tid + 256 * it;
            int row = cid >> 4, cc = cid & 15;
            cpa16(wo_b + (row * 68 + cc * 4) * 4,
                  g_woT + (size_t)row * 512 + kc * 128 + cc * 8);
        }
        asm volatile("cp.async.commit_group;" ::: "memory");
    };
    issueA(0, 0);

    // ---------------- Phase A: outproj GEMM (M=32), double-buffered ---
    float c[2][4] = {};
#pragma unroll
    for (int kc = 0; kc < 4; kc++) {
        const int buf = kc & 1;
        if (kc < 3) issueA(kc + 1, buf ^ 1);
        if (kc < 3) { asm volatile("cp.async.wait_group 1;" ::: "memory"); }
        else        { asm volatile("cp.async.wait_group 0;" ::: "memory"); }
        __syncthreads();

        const uint32_t ctxs_b = base + buf * 26112;
        const uint32_t wos_b  = ctxs_b + 8704;
#pragma unroll
        for (int kp = 0; kp < 4; kp++) {
            uint32_t a0[4], a1[4];
            uint32_t arow = ctxs_b + (mb * 16 + (lane & 15)) * 272
                            + (kp * 32 + (lane >> 4) * 8) * 2;
            ldm_x4(a0, arow);
            ldm_x4(a1, arow + 32);
#pragma unroll
            for (int nb = 0; nb < 2; nb++) {
                uint32_t b[4];
                ldm_x4(b, wos_b + (ng * 16 + nb * 8 + (lane & 7)) * 272
                              + (kp * 32 + (lane >> 3) * 8) * 2);
                mma16816(c[nb], a0, b[0], b[1]);
                mma16816(c[nb], a1, b[2], b[3]);
            }
        }
        __syncthreads();
    }
    // epilogue A: +bout, GELU, +x residual -> x2s
#pragma unroll
    for (int nb = 0; nb < 2; nb++) {
        int col = ng * 16 + nb * 8 + qc * 2;
        float bj0 = bout[col], bj1 = bout[col + 1];
#pragma unroll
        for (int hf = 0; hf < 2; hf++) {
            int row = mb * 16 + qr + hf * 8;
            float xv0 = x[(m0 + row) * 64 + col];
            float xv1 = x[(m0 + row) * 64 + col + 1];
            x2s[row * 64 + col]     = gelu(c[nb][hf * 2]     + bj0) + xv0;
            x2s[row * 64 + col + 1] = gelu(c[nb][hf * 2 + 1] + bj1) + xv1;
        }
    }
    __syncthreads();

    // ---------------- Phase B: LN2 (32 rows, 4 rows/warp) -------------
    {
        const float g2a = g2[lane], g2b = g2[lane + 32];
        const float bea = be2[lane], beb = be2[lane + 32];
        __half* ysh = (__half*)dynsm;
#pragma unroll
        for (int rr = 0; rr < 4; rr++) {
            int row = wid * 4 + rr;
            float a = x2s[row * 64 + lane], b = x2s[row * 64 + lane + 32];
            float s = a + b;
#pragma unroll
            for (int o = 16; o; o >>= 1) s += __shfl_xor_sync(0xffffffffu, s, o);
            float mean = s * (1.0f / 64.0f);
            float da = a - mean, db = b - mean;
            float q = da * da + db * db;
#pragma unroll
            for (int o = 16; o; o >>= 1) q += __shfl_xor_sync(0xffffffffu, q, o);
            float rstd = rsqrtf(q * (1.0f / 64.0f) + EPS);
            ysh[row * 72 + lane]      = __float2half(da * rstd * g2a + bea);
            ysh[row * 72 + lane + 32] = __float2half(db * rstd * g2b + beb);
        }
    }
    __syncthreads();

    // ---------------- Phase C: MLP ----------------
    float c2[2][4] = {};
#pragma unroll
    for (int kp = 0; kp < 2; kp++) {
        uint32_t a0[4], a1[4];
        uint32_t arow = y2s_b + (mb * 16 + (lane & 15)) * 144
                        + (kp * 32 + (lane >> 4) * 8) * 2;
        ldm_x4(a0, arow);
        ldm_x4(a1, arow + 32);
#pragma unroll
        for (int nb = 0; nb < 2; nb++) {
            uint32_t b[4];
            ldm_x4(b, w1s_b + (ng * 16 + nb * 8 + (lane & 7)) * 144
                          + (kp * 32 + (lane >> 3) * 8) * 2);
            mma16816(c2[nb], a0, b[0], b[1]);
            mma16816(c2[nb], a1, b[2], b[3]);
        }
    }
    {
        __half* hsh = (__half*)(dynsm + 4608);
#pragma unroll
        for (int nb = 0; nb < 2; nb++) {
            int col = ng * 16 + nb * 8 + qc * 2;
            float bj0 = b1[col], bj1 = b1[col + 1];
#pragma unroll
            for (int hf = 0; hf < 2; hf++) {
                int row = mb * 16 + qr + hf * 8;
                *(__half2*)(hsh + row * 72 + col) = __floats2half2_rn(
                    gelu(c2[nb][hf * 2] + bj0), gelu(c2[nb][hf * 2 + 1] + bj1));
            }
        }
    }
    __syncthreads();

    float c3[2][4] = {};
#pragma unroll
    for (int kp = 0; kp < 2; kp++) {
        uint32_t a0[4], a1[4];
        uint32_t arow = hs_b + (mb * 16 + (lane & 15)) * 144
                        + (kp * 32 + (lane >> 4) * 8) * 2;
        ldm_x4(a0, arow);
        ldm_x4(a1, arow + 32);
#pragma unroll
        for (int nb = 0; nb < 2; nb++) {
            uint32_t b[4];
            ldm_x4(b, w2s_b + (ng * 16 + nb * 8 + (lane & 7)) * 144
                          + (kp * 32 + (lane >> 3) * 8) * 2);
            mma16816(c3[nb], a0, b[0], b[1]);
            mma16816(c3[nb], a1, b[2], b[3]);
        }
    }
#pragma unroll
    for (int nb = 0; nb < 2; nb++) {
        int col = ng * 16 + nb * 8 + qc * 2;
        float bj0 = b2[col], bj1 = b2[col + 1];
#pragma unroll
        for (int hf = 0; hf < 2; hf++) {
            int row = mb * 16 + qr + hf * 8;
            out[(m0 + row) * 64 + col]     = c3[nb][hf * 2]     + bj0 + x2s[row * 64 + col];
            out[(m0 + row) * 64 + col + 1] = c3[nb][hf * 2 + 1] + bj1 + x2s[row * 64 + col + 1];
        }
    }
}

// =====================================================================
extern "C" void kernel_launch(void* const* d_in, const int* in_sizes, int n_in,
                              void* d_out, int out_size)
{
    const float* x    = (const float*)d_in[0];
    const float* g1   = (const float*)d_in[1];
    const float* be1  = (const float*)d_in[2];
    const float* Wqkv = (const float*)d_in[3];
    const float* bqkv = (const float*)d_in[4];
    const float* Wout = (const float*)d_in[5];
    const float* bout = (const float*)d_in[6];
    const float* g2   = (const float*)d_in[7];
    const float* be2  = (const float*)d_in[8];
    const float* W1   = (const float*)d_in[9];
    const float* b1   = (const float*)d_in[10];
    const float* W2   = (const float*)d_in[11];
    const float* b2   = (const float*)d_in[12];
    float* out = (float*)d_out;

    cudaFuncSetAttribute(attn_kernel,
                         cudaFuncAttributeMaxDynamicSharedMemorySize, ATTN_SMEM);
    cudaFuncSetAttribute(fused_tail_kernel,
                         cudaFuncAttributeMaxDynamicSharedMemorySize, FUSED_SMEM);

    wt_kernel<<<544, 256>>>(Wqkv, Wout, W1, W2);
    ln_qkv_kernel<<<dim3(128, 2), 128>>>(x, g1, be1, bqkv);
    attn_kernel<<<dim3(32, 32), 128, ATTN_SMEM>>>();
    fused_tail_kernel<<<256, 256, FUSED_SMEM>>>(x, bout, g2, be2, b1, b2, out);
}

// round 17
// speedup vs baseline: 1.1560x; 1.1560x over previous
#include <cuda_runtime.h>
#include <cuda_fp16.h>
#include <math.h>
#include <stdint.h>

// ---------------- problem constants ----------------
#define B_  4
#define N_  2048
#define C_  64
#define HS_ 512
#define H_  8
#define D_  64
#define M_  (B_*N_)
#define EPS 1e-6f
#define QSCALE 0.1803368801111144f   // log2(e)/8

#define QSZ (B_*H_*N_*D_)

// ---------------- scratch ----------------
__device__ __half g_qh[QSZ];          // [b*h][n][d], pre-scaled log2e/8
__device__ __half g_kh[QSZ];
__device__ __half g_vh[QSZ];
__device__ __half g_wT [1536 * 64];   // WqkvT fp16 [n][k]
__device__ __half g_woT[64 * 512];
__device__ __half g_w1T[64 * 64];
__device__ __half g_w2T[64 * 64];
__device__ __half g_ctxh[M_ * HS_];   // attention output fp16 (b,n,h*64+d)

__device__ __forceinline__ uint32_t smem_u32(const void* p) {
    uint32_t a;
    asm("{ .reg .u64 t; cvta.to.shared.u64 t, %1; cvt.u32.u64 %0, t; }" : "=r"(a) : "l"(p));
    return a;
}
__device__ __forceinline__ void mma16816(float c[4], const uint32_t a[4],
                                         uint32_t b0, uint32_t b1) {
    asm volatile("mma.sync.aligned.m16n8k16.row.col.f32.f16.f16.f32 "
        "{%0,%1,%2,%3}, {%4,%5,%6,%7}, {%8,%9}, {%0,%1,%2,%3};"
        : "+f"(c[0]), "+f"(c[1]), "+f"(c[2]), "+f"(c[3])
        : "r"(a[0]), "r"(a[1]), "r"(a[2]), "r"(a[3]), "r"(b0), "r"(b1));
}
// f16-accumulator HMMA
__device__ __forceinline__ void mma16816h(uint32_t c[2], const uint32_t a[4],
                                          uint32_t b0, uint32_t b1) {
    asm volatile("mma.sync.aligned.m16n8k16.row.col.f16.f16.f16.f16 "
        "{%0,%1}, {%2,%3,%4,%5}, {%6,%7}, {%0,%1};"
        : "+r"(c[0]), "+r"(c[1])
        : "r"(a[0]), "r"(a[1]), "r"(a[2]), "r"(a[3]), "r"(b0), "r"(b1));
}
__device__ __forceinline__ void ldm_x4(uint32_t r[4], uint32_t addr) {
    asm volatile("ldmatrix.sync.aligned.m8n8.x4.shared.b16 {%0,%1,%2,%3}, [%4];"
        : "=r"(r[0]), "=r"(r[1]), "=r"(r[2]), "=r"(r[3]) : "r"(addr));
}
__device__ __forceinline__ void ldm_x4_t(uint32_t r[4], uint32_t addr) {
    asm volatile("ldmatrix.sync.aligned.m8n8.x4.trans.shared.b16 {%0,%1,%2,%3}, [%4];"
        : "=r"(r[0]), "=r"(r[1]), "=r"(r[2]), "=r"(r[3]) : "r"(addr));
}
__device__ __forceinline__ uint32_t ex2h2(uint32_t x) {
    asm("ex2.approx.f16x2 %0, %0;" : "+r"(x));
    return x;
}
__device__ __forceinline__ void cpa16(uint32_t dst, const void* src) {
    asm volatile("cp.async.ca.shared.global [%0], [%1], 16;" :: "r"(dst), "l"(src) : "memory");
}
__device__ __forceinline__ float gelu(float v) {
    return 0.5f * v * (1.0f + erff(v * 0.70710678118f));
}

// =====================================================================
// Kernel 0: all weight prep (fp32 -> fp16 transposed)
// =====================================================================
__global__ __launch_bounds__(256) void wt_kernel(
    const float* __restrict__ Wqkv, const float* __restrict__ Wout,
    const float* __restrict__ W1, const float* __restrict__ W2)
{
    int idx = blockIdx.x * 256 + threadIdx.x;   // 139264 total
    if (idx < 98304) {
        int k = idx / 1536, n = idx - k * 1536;
        g_wT[n * 64 + k] = __float2half(Wqkv[idx]);
    } else if (idx < 131072) {
        int i = idx - 98304; int k = i >> 6, n = i & 63;
        g_woT[n * 512 + k] = __float2half(Wout[i]);
    } else if (idx < 135168) {
        int i = idx - 131072; int k = i >> 6, n = i & 63;
        g_w1T[n * 64 + k] = __float2half(W1[i]);
    } else {
        int i = idx - 135168; int k = i >> 6, n = i & 63;
        g_w2T[n * 64 + k] = __float2half(W2[i]);
    }
}

// =====================================================================
// Kernel 1: LN1 + QKV GEMM (fp16 mma). grid (128 m-tiles, 4 j-groups),
// 128 threads. Each CTA: LN (redundant, cheap) + 3 j-tiles of 128.
// =====================================================================
__global__ __launch_bounds__(128) void ln_qkv_kernel(
    const float* __restrict__ x, const float* __restrict__ g1,
    const float* __restrict__ be1, const float* __restrict__ bias)
{
    __shared__ __align__(16) uint32_t Ys[64 * 36];
    __shared__ __align__(16) uint32_t Ws[2][128 * 36];

    const int tid = threadIdx.x, wid = tid >> 5, lane = tid & 31;
    const int qr = lane >> 2, qc = lane & 3;
    const int m0 = blockIdx.x * 64;
    const int jt0 = blockIdx.y * 3;
    const uint32_t* wtw = (const uint32_t*)g_wT;

    auto issueW = [&](int jt, int buf) {
#pragma unroll
        for (int it = 0; it < 8; it++) {
            int cid = tid + 128 * it;               // 1024 chunks of 16B
            int row = cid >> 3, cc = cid & 7;
            cpa16(smem_u32(&Ws[buf][row * 36 + cc * 4]),
                  wtw + ((jt0 + jt) * 128 + row) * 32 + cc * 4);
        }
        asm volatile("cp.async.commit_group;" ::: "memory");
    };
    issueW(0, 0);

    {
        const float g1a = g1[lane], g1b = g1[lane + 32];
        const float bea = be1[lane], beb = be1[lane + 32];
        __half* ysh = (__half*)Ys;
#pragma unroll
        for (int rr = 0; rr < 16; rr++) {
            int row = wid * 16 + rr;
            float a = x[(m0 + row) * 64 + lane];
            float b = x[(m0 + row) * 64 + lane + 32];
            float s = a + b;
#pragma unroll
            for (int o = 16; o; o >>= 1) s += __shfl_xor_sync(0xffffffffu, s, o);
            float mean = s * (1.0f / 64.0f);
            float da = a - mean, db = b - mean;
            float q = da * da + db * db;
#pragma unroll
            for (int o = 16; o; o >>= 1) q += __shfl_xor_sync(0xffffffffu, q, o);
            float rstd = rsqrtf(q * (1.0f / 64.0f) + EPS);
            ysh[row * 72 + lane]      = __float2half(da * rstd * g1a + bea);
            ysh[row * 72 + lane + 32] = __float2half(db * rstd * g1b + beb);
        }
    }
    __syncthreads();

    const uint32_t ys_base = smem_u32(Ys);
    uint32_t a[4][4][4];
#pragma unroll
    for (int m = 0; m < 4; m++)
#pragma unroll
        for (int kc = 0; kc < 4; kc++)
            ldm_x4(a[m][kc], ys_base + (m * 16 + (lane & 15)) * 144
                              + (kc * 16 + (lane >> 4) * 8) * 2);

    for (int jt = 0; jt < 3; jt++) {
        const int buf = jt & 1;
        asm volatile("cp.async.wait_group 0;" ::: "memory");
        __syncthreads();
        if (jt < 2) issueW(jt + 1, buf ^ 1);

        const uint32_t ws_base = smem_u32(&Ws[buf][0]);
        float c[4][4][4] = {};
#pragma unroll
        for (int kcp = 0; kcp < 2; kcp++) {
#pragma unroll
            for (int nb = 0; nb < 4; nb++) {
                uint32_t b[4];
                ldm_x4(b, ws_base + (wid * 32 + nb * 8 + (lane & 7)) * 144
                              + (kcp * 32 + (lane >> 3) * 8) * 2);
#pragma unroll
                for (int m = 0; m < 4; m++) {
                    mma16816(c[m][nb], a[m][2 * kcp],     b[0], b[1]);
                    mma16816(c[m][nb], a[m][2 * kcp + 1], b[2], b[3]);
                }
            }
        }
        const int j0 = (jt0 + jt) * 128;
#pragma unroll
        for (int nb = 0; nb < 4; nb++) {
            int j = j0 + wid * 32 + nb * 8 + qc * 2;
            int sel = j >> 9, head = (j >> 6) & 7, d = j & 63;
            float bj0 = bias[j], bj1 = bias[j + 1];
            float sc = (sel == 0) ? QSCALE : 1.0f;
            __half* dst = (sel == 0) ? g_qh : (sel == 1) ? g_kh : g_vh;
#pragma unroll
            for (int m = 0; m < 4; m++) {
#pragma unroll
                for (int hf = 0; hf < 2; hf++) {
                    int gm = m0 + m * 16 + qr + hf * 8;
                    int bi = gm >> 11, n = gm & 2047;
                    float v0 = (c[m][nb][hf * 2]     + bj0) * sc;
                    float v1 = (c[m][nb][hf * 2 + 1] + bj1) * sc;
                    size_t off = ((size_t)(bi * 8 + head) * 2048 + n) * 64 + d;
                    *(__half2*)(dst + off) = __floats2half2_rn(v0, v1);
                }
            }
        }
    }
}

// =====================================================================
// Kernel 2: flash attention (proven round-11/13/14 core, static smem,
// 2-buffer cp.async, f16-accum S phase, in-place ex2).
// =====================================================================
__global__ __launch_bounds__(128) void attn_kernel()
{
    __shared__ __align__(16) uint32_t Qs[64 * 36];
    __shared__ __align__(16) uint32_t KV[2][2][64 * 36];

    const int tid = threadIdx.x, wid = tid >> 5, lane = tid & 31;
    const int qr = lane >> 2, qc = lane & 3;
    const int bh = blockIdx.y, q0 = blockIdx.x * 64;
    const uint32_t* qb = (const uint32_t*)(g_qh + (size_t)bh * N_ * D_);
    const __half* kbh = g_kh + (size_t)bh * N_ * D_;
    const __half* vbh = g_vh + (size_t)bh * N_ * D_;

#pragma unroll
    for (int r = 0; r < 16; r++) {
        int idx = tid + 128 * r; int row = idx >> 5, w = idx & 31;
        Qs[row * 36 + w] = qb[(q0 + row) * 32 + w];
    }

    auto issue = [&](int kt, int buf) {
#pragma unroll
        for (int it = 0; it < 8; it++) {
            int cid = tid + 128 * it;
            int tsel = cid >> 9, r = (cid >> 3) & 63, cc = cid & 7;
            const __half* src = (tsel ? vbh : kbh) + (size_t)(kt * 64 + r) * 64 + cc * 8;
            cpa16(smem_u32(&KV[buf][tsel][r * 36 + cc * 4]), src);
        }
        asm volatile("cp.async.commit_group;" ::: "memory");
    };
    issue(0, 0);
    __syncthreads();

    uint32_t aq[4][4];
#pragma unroll
    for (int kc = 0; kc < 4; kc++) {
        aq[kc][0] = Qs[(wid * 16 + qr) * 36 + kc * 8 + qc];
        aq[kc][1] = Qs[(wid * 16 + qr + 8) * 36 + kc * 8 + qc];
        aq[kc][2] = Qs[(wid * 16 + qr) * 36 + kc * 8 + 4 + qc];
        aq[kc][3] = Qs[(wid * 16 + qr + 8) * 36 + kc * 8 + 4 + qc];
    }

    float oacc[8][4] = {};
    float lsum0 = 0.0f, lsum1 = 0.0f;

    for (int kt = 0; kt < 32; kt++) {
        const int buf = kt & 1;
        asm volatile("cp.async.wait_group 0;" ::: "memory");
        __syncthreads();
        if (kt < 31) issue(kt + 1, buf ^ 1);

        const uint32_t Kbase = smem_u32(&KV[buf][0][0]);
        const uint32_t Vbase = smem_u32(&KV[buf][1][0]);

        uint32_t sp[8][2] = {};
#pragma unroll
        for (int nb = 0; nb < 8; nb++) {
            uint32_t rowb = (nb * 8 + (lane & 7)) * 144;
#pragma unroll
            for (int kcp = 0; kcp < 2; kcp++) {
                uint32_t b[4];
                ldm_x4(b, Kbase + rowb + (kcp * 32 + (lane >> 3) * 8) * 2);
                mma16816h(sp[nb], aq[2 * kcp],     b[0], b[1]);
                mma16816h(sp[nb], aq[2 * kcp + 1], b[2], b[3]);
            }
        }

        __half2 t0 = __floats2half2_rn(0.0f, 0.0f), t1 = t0;
#pragma unroll
        for (int nb = 0; nb < 8; nb++) {
            sp[nb][0] = ex2h2(sp[nb][0]);
            sp[nb][1] = ex2h2(sp[nb][1]);
            t0 = __hadd2(t0, *(__half2*)&sp[nb][0]);
            t1 = __hadd2(t1, *(__half2*)&sp[nb][1]);
        }
        lsum0 += __low2float(t0) + __high2float(t0);
        lsum1 += __low2float(t1) + __high2float(t1);

#pragma unroll
        for (int nb = 0; nb < 8; nb++) {
#pragma unroll
            for (int kcp = 0; kcp < 2; kcp++) {
                uint32_t b[4];
                uint32_t row = kcp * 32 + (lane & 7) + (lane >> 3) * 8;
                ldm_x4_t(b, Vbase + row * 144 + nb * 16);
                uint32_t a0[4] = {sp[4 * kcp][0],     sp[4 * kcp][1],
                                  sp[4 * kcp + 1][0], sp[4 * kcp + 1][1]};
                uint32_t a1[4] = {sp[4 * kcp + 2][0], sp[4 * kcp + 2][1],
                                  sp[4 * kcp + 3][0], sp[4 * kcp + 3][1]};
                mma16816(oacc[nb], a0, b[0], b[1]);
                mma16816(oacc[nb], a1, b[2], b[3]);
            }
        }
    }

    lsum0 += __shfl_xor_sync(0xffffffffu, lsum0, 1);
    lsum0 += __shfl_xor_sync(0xffffffffu, lsum0, 2);
    lsum1 += __shfl_xor_sync(0xffffffffu, lsum1, 1);
    lsum1 += __shfl_xor_sync(0xffffffffu, lsum1, 2);
    const float inv0 = 1.0f / lsum0, inv1 = 1.0f / lsum1;

    const int bi = bh >> 3, head = bh & 7;
    const int n0 = q0 + wid * 16 + qr;
#pragma unroll
    for (int nb = 0; nb < 8; nb++) {
        const int d = nb * 8 + qc * 2;
        *(__half2*)(g_ctxh + ((size_t)(bi * 2048 + n0)) * 512 + head * 64 + d) =
            __floats2half2_rn(oacc[nb][0] * inv0, oacc[nb][1] * inv0);
        *(__half2*)(g_ctxh + ((size_t)(bi * 2048 + n0 + 8)) * 512 + head * 64 + d) =
            __floats2half2_rn(oacc[nb][2] * inv1, oacc[nb][3] * inv1);
    }
}

// =====================================================================
// Kernel 3: FUSED tail (round-14 proven: 32-row tiles, K=128 chunks,
// double-buffered, W1/W2 prefetch). grid 256, 256 threads.
//   [0,8704)       ctx[0] 32x272B     | y2s (B/C) @0, hs @4608
//   [8704,26112)   wo[0]  64x272B
//   [26112,34816)  ctx[1]
//   [34816,52224)  wo[1]
//   [52224,60416)  x2s 32x64 f32
//   [60416,69632)  W1s 64x144B
//   [69632,78848)  W2s
// =====================================================================
#define FUSED_SMEM 78848

__global__ __launch_bounds__(256) void fused_tail_kernel(
    const float* __restrict__ x, const float* __restrict__ bout,
    const float* __restrict__ g2, const float* __restrict__ be2,
    const float* __restrict__ b1, const float* __restrict__ b2,
    float* __restrict__ out)
{
    extern __shared__ __align__(16) unsigned char dynsm[];
    float* x2s = (float*)(dynsm + 52224);
    const uint32_t base = smem_u32(dynsm);
    const uint32_t y2s_b = base, hs_b = base + 4608;
    const uint32_t w1s_b = base + 60416, w2s_b = base + 69632;

    const int tid = threadIdx.x, wid = tid >> 5, lane = tid & 31;
    const int qr = lane >> 2, qc = lane & 3;
    const int mb = wid & 1, ng = wid >> 1;
    const int m0 = blockIdx.x * 32;

    // prefetch W1/W2 (16KB = 1024 chunks of 16B) as the FIRST group
#pragma unroll
    for (int it = 0; it < 4; it++) {
        int cid = tid + 256 * it;                 // 0..1023
        int sel = cid >> 9, r = (cid >> 3) & 63, cc = cid & 7;
        uint32_t dst = (sel ? w2s_b : w1s_b) + (r * 36 + cc * 4) * 4;
        const uint32_t* src = (const uint32_t*)(sel ? g_w2T : g_w1T) + r * 32 + cc * 4;
        cpa16(dst, src);
    }
    asm volatile("cp.async.commit_group;" ::: "memory");

    auto issueA = [&](int kc, int buf) {
        uint32_t ctx_b = base + buf * 26112;
        uint32_t wo_b  = ctx_b + 8704;
        // ctx: 32 rows x 128 halves = 512 chunks
#pragma unroll
        for (int it = 0; it < 2; it++) {
            int cid = tid + 256 * it;
            int row = cid >> 4, cc = cid & 15;
            cpa16(ctx_b + (row * 68 + cc * 4) * 4,
                  g_ctxh + (size_t)(m0 + row) * 512 + kc * 128 + cc * 8);
        }
        // wo: 64 rows x 128 halves = 1024 chunks
#pragma unroll
        for (int it = 0; it < 4; it++) {
            int cid = tid + 256 * it;
            int row = cid >> 4, cc = cid & 15;
            cpa16(wo_b + (row * 68 + cc * 4) * 4,
                  g_woT + (size_t)row * 512 + kc * 128 + cc * 8);
        }
        asm volatile("cp.async.commit_group;" ::: "memory");
    };
    issueA(0, 0);

    // ---------------- Phase A: outproj GEMM (M=32), double-buffered ---
    float c[2][4] = {};
#pragma unroll
    for (int kc = 0; kc < 4; kc++) {
        const int buf = kc & 1;
        if (kc < 3) issueA(kc + 1, buf ^ 1);
        if (kc < 3) { asm volatile("cp.async.wait_group 1;" ::: "memory"); }
        else        { asm volatile("cp.async.wait_group 0;" ::: "memory"); }
        __syncthreads();

        const uint32_t ctxs_b = base + buf * 26112;
        const uint32_t wos_b  = ctxs_b + 8704;
#pragma unroll
        for (int kp = 0; kp < 4; kp++) {
            uint32_t a0[4], a1[4];
            uint32_t arow = ctxs_b + (mb * 16 + (lane & 15)) * 272
                            + (kp * 32 + (lane >> 4) * 8) * 2;
            ldm_x4(a0, arow);
            ldm_x4(a1, arow + 32);
#pragma unroll
            for (int nb = 0; nb < 2; nb++) {
                uint32_t b[4];
                ldm_x4(b, wos_b + (ng * 16 + nb * 8 + (lane & 7)) * 272
                              + (kp * 32 + (lane >> 3) * 8) * 2);
                mma16816(c[nb], a0, b[0], b[1]);
                mma16816(c[nb], a1, b[2], b[3]);
            }
        }
        __syncthreads();
    }
    // epilogue A: +bout, GELU, +x residual -> x2s
#pragma unroll
    for (int nb = 0; nb < 2; nb++) {
        int col = ng * 16 + nb * 8 + qc * 2;
        float bj0 = bout[col], bj1 = bout[col + 1];
#pragma unroll
        for (int hf = 0; hf < 2; hf++) {
            int row = mb * 16 + qr + hf * 8;
            float xv0 = x[(m0 + row) * 64 + col];
            float xv1 = x[(m0 + row) * 64 + col + 1];
            x2s[row * 64 + col]     = gelu(c[nb][hf * 2]     + bj0) + xv0;
            x2s[row * 64 + col + 1] = gelu(c[nb][hf * 2 + 1] + bj1) + xv1;
        }
    }
    __syncthreads();

    // ---------------- Phase B: LN2 (32 rows, 4 rows/warp) -------------
    {
        const float g2a = g2[lane], g2b = g2[lane + 32];
        const float bea = be2[lane], beb = be2[lane + 32];
        __half* ysh = (__half*)dynsm;
#pragma unroll
        for (int rr = 0; rr < 4; rr++) {
            int row = wid * 4 + rr;
            float a = x2s[row * 64 + lane], b = x2s[row * 64 + lane + 32];
            float s = a + b;
#pragma unroll
            for (int o = 16; o; o >>= 1) s += __shfl_xor_sync(0xffffffffu, s, o);
            float mean = s * (1.0f / 64.0f);
            float da = a - mean, db = b - mean;
            float q = da * da + db * db;
#pragma unroll
            for (int o = 16; o; o >>= 1) q += __shfl_xor_sync(0xffffffffu, q, o);
            float rstd = rsqrtf(q * (1.0f / 64.0f) + EPS);
            ysh[row * 72 + lane]      = __float2half(da * rstd * g2a + bea);
            ysh[row * 72 + lane + 32] = __float2half(db * rstd * g2b + beb);
        }
    }
    __syncthreads();

    // ---------------- Phase C: MLP ----------------
    float c2[2][4] = {};
#pragma unroll
    for (int kp = 0; kp < 2; kp++) {
        uint32_t a0[4], a1[4];
        uint32_t arow = y2s_b + (mb * 16 + (lane & 15)) * 144
                        + (kp * 32 + (lane >> 4) * 8) * 2;
        ldm_x4(a0, arow);
        ldm_x4(a1, arow + 32);
#pragma unroll
        for (int nb = 0; nb < 2; nb++) {
            uint32_t b[4];
            ldm_x4(b, w1s_b + (ng * 16 + nb * 8 + (lane & 7)) * 144
                          + (kp * 32 + (lane >> 3) * 8) * 2);
            mma16816(c2[nb], a0, b[0], b[1]);
            mma16816(c2[nb], a1, b[2], b[3]);
        }
    }
    {
        __half* hsh = (__half*)(dynsm + 4608);
#pragma unroll
        for (int nb = 0; nb < 2; nb++) {
            int col = ng * 16 + nb * 8 + qc * 2;
            float bj0 = b1[col], bj1 = b1[col + 1];
#pragma unroll
            for (int hf = 0; hf < 2; hf++) {
                int row = mb * 16 + qr + hf * 8;
                *(__half2*)(hsh + row * 72 + col) = __floats2half2_rn(
                    gelu(c2[nb][hf * 2] + bj0), gelu(c2[nb][hf * 2 + 1] + bj1));
            }
        }
    }
    __syncthreads();

    float c3[2][4] = {};
#pragma unroll
    for (int kp = 0; kp < 2; kp++) {
        uint32_t a0[4], a1[4];
        uint32_t arow = hs_b + (mb * 16 + (lane & 15)) * 144
                        + (kp * 32 + (lane >> 4) * 8) * 2;
        ldm_x4(a0, arow);
        ldm_x4(a1, arow + 32);
#pragma unroll
        for (int nb = 0; nb < 2; nb++) {
            uint32_t b[4];
            ldm_x4(b, w2s_b + (ng * 16 + nb * 8 + (lane & 7)) * 144
                          + (kp * 32 + (lane >> 3) * 8) * 2);
            mma16816(c3[nb], a0, b[0], b[1]);
            mma16816(c3[nb], a1, b[2], b[3]);
        }
    }
#pragma unroll
    for (int nb = 0; nb < 2; nb++) {
        int col = ng * 16 + nb * 8 + qc * 2;
        float bj0 = b2[col], bj1 = b2[col + 1];
#pragma unroll
        for (int hf = 0; hf < 2; hf++) {
            int row = mb * 16 + qr + hf * 8;
            out[(m0 + row) * 64 + col]     = c3[nb][hf * 2]     + bj0 + x2s[row * 64 + col];
            out[(m0 + row) * 64 + col + 1] = c3[nb][hf * 2 + 1] + bj1 + x2s[row * 64 + col + 1];
        }
    }
}

// =====================================================================
extern "C" void kernel_launch(void* const* d_in, const int* in_sizes, int n_in,
                              void* d_out, int out_size)
{
    const float* x    = (const float*)d_in[0];
    const float* g1   = (const float*)d_in[1];
    const float* be1  = (const float*)d_in[2];
    const float* Wqkv = (const float*)d_in[3];
    const float* bqkv = (const float*)d_in[4];
    const float* Wout = (const float*)d_in[5];
    const float* bout = (const float*)d_in[6];
    const float* g2   = (const float*)d_in[7];
    const float* be2  = (const float*)d_in[8];
    const float* W1   = (const float*)d_in[9];
    const float* b1   = (const float*)d_in[10];
    const float* W2   = (const float*)d_in[11];
    const float* b2   = (const float*)d_in[12];
    float* out = (float*)d_out;

    cudaFuncSetAttribute(fused_tail_kernel,
                         cudaFuncAttributeMaxDynamicSharedMemorySize, FUSED_SMEM);

    wt_kernel<<<544, 256>>>(Wqkv, Wout, W1, W2);
    ln_qkv_kernel<<<dim3(128, 4), 128>>>(x, g1, be1, bqkv);
    attn_kernel<<<dim3(32, 32), 128>>>();
    fused_tail_kernel<<<256, 256, FUSED_SMEM>>>(x, bout, g2, be2, b1, b2, out);
}